// round 15
// baseline (speedup 1.0000x reference)
#include <cuda_runtime.h>
#include <cuda_fp16.h>
#include <cstdint>

#define BATCH 32
#define TSEQ  48
#define EDIM  128
#define TDIM  48
#define DIN   176
#define HDIM  256
#define GDIM  768
#define OUTL  40000
#define OUTC  40048
#define MROWS 1536
#define NTILES 313            /* ceil(40048/128) */
#define NPAD  (NTILES * 128)  /* 40064 */
#define LOG2E 1.4426950408889634f

// ------------------ device scratch (no allocation allowed) ------------------
__device__ float g_X0[MROWS * DIN];
__device__ float g_XP[MROWS * GDIM];
__device__ float g_Y0[MROWS * HDIM];
__device__ float g_Y1[MROWS * HDIM];
__device__ uint4 g_Apack[(MROWS / 16) * 16 * 32];
__device__ uint2 g_Bpack[(NPAD / 8) * 16 * 32];
__device__ float g_ploc[NTILES * MROWS];   // [tile][row] for coalesced reduce
__device__ float g_ptm[MROWS];
__device__ float g_lse[MROWS * 2];

// ------------------ helpers ------------------
__device__ __forceinline__ uint32_t smem_u32(const void* p) {
    uint32_t a;
    asm("{ .reg .u64 t; cvta.to.shared.u64 t, %1; cvt.u32.u64 %0, t; }" : "=r"(a) : "l"(p));
    return a;
}
__device__ __forceinline__ uint32_t pk(float a, float b) {
    __half2 h = __floats2half2_rn(a, b);
    return *(uint32_t*)&h;
}
__device__ __forceinline__ __half2 u2h(uint32_t v) { return *(__half2*)&v; }
__device__ __forceinline__ void cluster_barrier() {
    asm volatile("barrier.cluster.arrive.aligned;\n\tbarrier.cluster.wait.aligned;" ::: "memory");
}
__device__ __forceinline__ void mbar_init(uint32_t mbar, uint32_t cnt) {
    asm volatile("mbarrier.init.shared.b64 [%0], %1;" :: "r"(mbar), "r"(cnt) : "memory");
}
__device__ __forceinline__ void mbar_expect_tx(uint32_t mbar, uint32_t bytes) {
    asm volatile("mbarrier.arrive.expect_tx.shared.b64 _, [%0], %1;"
                 :: "r"(mbar), "r"(bytes) : "memory");
}
__device__ __forceinline__ void mbar_wait(uint32_t mbar, uint32_t parity) {
    asm volatile(
        "{\n\t"
        ".reg .pred P;\n\t"
        "LAB_WAIT_%=:\n\t"
        "mbarrier.try_wait.parity.acquire.cluster.shared::cta.b64 P, [%0], %1, 0x989680;\n\t"
        "@P bra LAB_DONE_%=;\n\t"
        "bra LAB_WAIT_%=;\n\t"
        "LAB_DONE_%=:\n\t"
        "}"
        :: "r"(mbar), "r"(parity) : "memory");
}
// store 4 bytes into remote CTA rk's smem with tx-arrive on its mbarrier
__device__ __forceinline__ void st_async_remote(uint32_t laddr, uint32_t lmbar,
                                                uint32_t rk, uint32_t val) {
    asm volatile(
        "{\n\t"
        ".reg .b32 ra, rb;\n\t"
        "mapa.shared::cluster.u32 ra, %0, %2;\n\t"
        "mapa.shared::cluster.u32 rb, %1, %2;\n\t"
        "st.async.shared::cluster.mbarrier::complete_tx::bytes.b32 [ra], %3, [rb];\n\t"
        "}"
        :: "r"(laddr), "r"(lmbar), "r"(rk), "r"(val) : "memory");
}

// ------------------ K0: embedding gather + one-hot time ------------------
__global__ void k_embed(const int* __restrict__ loc, const int* __restrict__ tim,
                        const float* __restrict__ emb, float* __restrict__ X0) {
    int idx = blockIdx.x * blockDim.x + threadIdx.x;
    if (idx >= MROWS * DIN) return;
    int m = idx / DIN, c = idx - m * DIN;
    float v;
    if (c < EDIM) v = emb[(size_t)loc[m] * EDIM + c];
    else          v = (tim[m] == (c - EDIM)) ? 1.0f : 0.0f;
    X0[idx] = v;
}

// ------------------ K1: fp32 GEMM  C[M,N] = A[M,K] @ W[N,K]^T + bias -------
__global__ void __launch_bounds__(256) k_gemm64(const float* __restrict__ A,
                                                const float* __restrict__ W,
                                                const float* __restrict__ bias,
                                                float* __restrict__ C,
                                                int M, int N, int K) {
    __shared__ float As[16][68];
    __shared__ float Bs[16][68];
    int tid = threadIdx.x;
    int bm = blockIdx.y * 64, bn = blockIdx.x * 64;
    int tx = tid & 15, ty = tid >> 4;
    int lr = tid >> 2, lc = (tid & 3) * 4;
    float acc[4][4] = {};
    for (int k0 = 0; k0 < K; k0 += 16) {
        float4 a = *(const float4*)(A + (size_t)(bm + lr) * K + k0 + lc);
        float4 w = *(const float4*)(W + (size_t)(bn + lr) * K + k0 + lc);
        As[lc + 0][lr] = a.x; As[lc + 1][lr] = a.y; As[lc + 2][lr] = a.z; As[lc + 3][lr] = a.w;
        Bs[lc + 0][lr] = w.x; Bs[lc + 1][lr] = w.y; Bs[lc + 2][lr] = w.z; Bs[lc + 3][lr] = w.w;
        __syncthreads();
#pragma unroll
        for (int kk = 0; kk < 16; kk++) {
            float4 av = *(const float4*)&As[kk][ty * 4];
            float4 bv = *(const float4*)&Bs[kk][tx * 4];
            float aa[4] = {av.x, av.y, av.z, av.w};
            float bb[4] = {bv.x, bv.y, bv.z, bv.w};
#pragma unroll
            for (int i = 0; i < 4; i++)
#pragma unroll
                for (int j = 0; j < 4; j++) acc[i][j] += aa[i] * bb[j];
        }
        __syncthreads();
    }
#pragma unroll
    for (int i = 0; i < 4; i++)
#pragma unroll
        for (int j = 0; j < 4; j++) {
            int n = bn + tx * 4 + j;
            C[(size_t)(bm + ty * 4 + i) * N + n] = acc[i][j] + bias[n];
        }
}

// ------------------ K2: GRU recurrence -------------------------------------
// Cluster of 4 CTAs per batch element; 384 threads/CTA. Weights in registers.
// ALL 48 steps of this CTA's xp slice staged in smem up-front (no LDG in the
// recurrence loop). Cross-CTA h exchange via st.async + dual mbarriers.
__global__ void __launch_bounds__(384, 1) __cluster_dims__(4, 1, 1)
k_rec(const float* __restrict__ xp, const float* __restrict__ w_hh,
      const float* __restrict__ b_hh, const float* __restrict__ traj,
      const int* __restrict__ labels, float* __restrict__ y, int layer) {
    __shared__ uint32_t HH[256];        // [2][128] half2 (double-buffered h)
    __shared__ float PP[384];           // half-row partial dots
    __shared__ float XPS[TSEQ * 192];   // all 48 steps of xp slice (36.9 KB)
    __shared__ __align__(8) unsigned long long MB[2];
    const int tid = threadIdx.x;
    const int b = blockIdx.x >> 2, part = blockIdx.x & 3;
    const uint32_t mb0 = smem_u32(&MB[0]);

    if (tid == 0) { mbar_init(mb0, 1); mbar_init(mb0 + 8, 1); }

    // register-resident weights: each thread owns half (128 elems) of one row
    const int half = (tid >= 192) ? 1 : 0;
    const int r = tid - half * 192;                    // 0..191
    const int row = (r >> 6) * 256 + part * 64 + (r & 63);
    const float* wr = w_hh + (size_t)row * 256 + half * 128;
    uint4 wreg[16];
#pragma unroll
    for (int k = 0; k < 16; k++) {
        float4 a = *(const float4*)(wr + k * 8);
        float4 c = *(const float4*)(wr + k * 8 + 4);
        wreg[k] = make_uint4(pk(a.x, a.y), pk(a.z, a.w), pk(c.x, c.y), pk(c.z, c.w));
    }

    const int lb = labels[layer * 16 + (b >> 1)];
    const float* h0p = traj + (size_t)lb * 512 + (b & 1) * 256;
    if (tid < 128) HH[tid] = pk(h0p[2 * tid], h0p[2 * tid + 1]);
    float h_own = (tid < 64) ? h0p[part * 64 + tid] : 0.f;
    float bhr = 0.f, bhz = 0.f, bhn = 0.f;
    if (tid < 64) {
        bhr = b_hh[part * 64 + tid];
        bhz = b_hh[256 + part * 64 + tid];
        bhn = b_hh[512 + part * 64 + tid];
    }
    // stage the whole xp slice: XPS[t*192 + s] = xp[(b*48+t)*768 + (s>>6)*256 + part*64 + (s&63)]
    {
        const float* xb = xp + (size_t)(b * 48) * 768 + part * 64;
        for (int i = tid; i < TSEQ * 192; i += 384) {
            int t = i / 192, s = i - t * 192;
            XPS[i] = xb[(size_t)t * 768 + (s >> 6) * 256 + (s & 63)];
        }
    }
    __syncthreads();
    cluster_barrier();   // mbarriers + initial HH visible cluster-wide

    for (int t = 0; t < 48; t++) {
        if (t >= 1) mbar_wait(mb0 + ((t - 1) & 1) * 8, ((t - 1) >> 1) & 1);
        if (tid == 0 && t < 47) mbar_expect_tx(mb0 + (t & 1) * 8, 512);
        {
            const uint4* h4 = (const uint4*)HH + (t & 1) * 32 + half * 16;
            float acc0 = 0.f, acc1 = 0.f;
#pragma unroll
            for (int k = 0; k < 16; k += 4) {
                uint4 ha = h4[k], hb = h4[k + 1], hc = h4[k + 2], hd = h4[k + 3];
                __half2 c0 = __float2half2_rn(0.f);
                c0 = __hfma2(u2h(wreg[k].x), u2h(ha.x), c0);
                c0 = __hfma2(u2h(wreg[k].y), u2h(ha.y), c0);
                c0 = __hfma2(u2h(wreg[k].z), u2h(ha.z), c0);
                c0 = __hfma2(u2h(wreg[k].w), u2h(ha.w), c0);
                c0 = __hfma2(u2h(wreg[k + 1].x), u2h(hb.x), c0);
                c0 = __hfma2(u2h(wreg[k + 1].y), u2h(hb.y), c0);
                c0 = __hfma2(u2h(wreg[k + 1].z), u2h(hb.z), c0);
                c0 = __hfma2(u2h(wreg[k + 1].w), u2h(hb.w), c0);
                __half2 c1 = __float2half2_rn(0.f);
                c1 = __hfma2(u2h(wreg[k + 2].x), u2h(hc.x), c1);
                c1 = __hfma2(u2h(wreg[k + 2].y), u2h(hc.y), c1);
                c1 = __hfma2(u2h(wreg[k + 2].z), u2h(hc.z), c1);
                c1 = __hfma2(u2h(wreg[k + 2].w), u2h(hc.w), c1);
                c1 = __hfma2(u2h(wreg[k + 3].x), u2h(hd.x), c1);
                c1 = __hfma2(u2h(wreg[k + 3].y), u2h(hd.y), c1);
                c1 = __hfma2(u2h(wreg[k + 3].z), u2h(hd.z), c1);
                c1 = __hfma2(u2h(wreg[k + 3].w), u2h(hd.w), c1);
                float2 f0 = __half22float2(c0);
                float2 f1 = __half22float2(c1);
                acc0 += f0.x + f0.y;
                acc1 += f1.x + f1.y;
            }
            PP[tid] = acc0 + acc1;
        }
        __syncthreads();
        if (tid < 64) {
            const float* xc = XPS + t * 192;
            float hr = PP[tid] + PP[192 + tid] + bhr;
            float hz = PP[64 + tid] + PP[256 + tid] + bhz;
            float hn = PP[128 + tid] + PP[320 + tid] + bhn;
            float r2 = 1.f / (1.f + __expf(-(xc[tid] + hr)));
            float z = 1.f / (1.f + __expf(-(xc[64 + tid] + hz)));
            float n = tanhf(xc[128 + tid] + r2 * hn);
            float hv = (1.f - z) * n + z * h_own;
            h_own = hv;
            y[(size_t)(b * 48 + t) * 256 + part * 64 + tid] = hv;
            float hvo = __shfl_xor_sync(0xffffffffu, hv, 1);
            if (!(tid & 1) && t < 47) {
                uint32_t pv = pk(hv, hvo);
                uint32_t la = smem_u32(&HH[((t + 1) & 1) * 128 + ((part * 64 + tid) >> 1)]);
                uint32_t lm = mb0 + (t & 1) * 8;
#pragma unroll
                for (int rk = 0; rk < 4; rk++) st_async_remote(la, lm, rk, pv);
            }
        }
    }
    cluster_barrier();   // no CTA exits while peers' st.asyncs may target it
}

// ------------------ K3: operand packing for fp16 mma ------------------
__global__ void k_packA() {
    int g = blockIdx.x * blockDim.x + threadIdx.x;
    if (g >= (MROWS / 16) * 16 * 32) return;
    int lane = g & 31, kt = (g >> 5) & 15, mt = g >> 9;
    int r = mt * 16 + (lane >> 2);
    int c0 = kt * 16 + (lane & 3) * 2;
    const float* p0 = g_Y1 + (size_t)r * HDIM + c0;
    const float* p1 = p0 + 8 * HDIM;
#define RL(x) fmaxf((x), 0.f)
    g_Apack[g] = make_uint4(pk(RL(p0[0]), RL(p0[1])), pk(RL(p1[0]), RL(p1[1])),
                            pk(RL(p0[8]), RL(p0[9])), pk(RL(p1[8]), RL(p1[9])));
#undef RL
}
__global__ void k_packB(const float* __restrict__ fw) {
    int g = blockIdx.x * blockDim.x + threadIdx.x;
    if (g >= (NPAD / 8) * 16 * 32) return;
    int lane = g & 31, kt = (g >> 5) & 15, nt = g >> 9;
    int n = nt * 8 + (lane >> 2);
    int k0 = kt * 16 + (lane & 3) * 2;
    float w00 = 0.f, w01 = 0.f, w08 = 0.f, w09 = 0.f;
    if (n < OUTC) {
        const float* r = fw + (size_t)n * HDIM + k0;
        w00 = r[0]; w01 = r[1]; w08 = r[8]; w09 = r[9];
    }
    g_Bpack[g] = make_uint2(pk(w00, w01), pk(w08, w09));
}

// ------------------ K4: fc GEMM (fp16 mma, fp32 acc) + write + exp sums ----
__global__ void __launch_bounds__(256) k_fc(const float* __restrict__ fc_b,
                                            float* __restrict__ out_loc,
                                            float* __restrict__ out_tm) {
    const int lane = threadIdx.x & 31, w = threadIdx.x >> 5;
    const int wm = (w >> 2) * 64, wn = (w & 3) * 32;
    const int m0 = blockIdx.y * 128, n0 = blockIdx.x * 128;
    const int mtb = (m0 + wm) >> 4, ntb = (n0 + wn) >> 3;
    float acc[4][4][4];
#pragma unroll
    for (int i = 0; i < 4; i++)
#pragma unroll
        for (int j = 0; j < 4; j++) {
            acc[i][j][0] = 0.f; acc[i][j][1] = 0.f; acc[i][j][2] = 0.f; acc[i][j][3] = 0.f;
        }
    for (int kt = 0; kt < 16; kt++) {
        uint4 af[4]; uint2 bf[4];
#pragma unroll
        for (int i = 0; i < 4; i++) af[i] = g_Apack[((size_t)(mtb + i) * 16 + kt) * 32 + lane];
#pragma unroll
        for (int j = 0; j < 4; j++) bf[j] = g_Bpack[((size_t)(ntb + j) * 16 + kt) * 32 + lane];
#pragma unroll
        for (int i = 0; i < 4; i++)
#pragma unroll
            for (int j = 0; j < 4; j++)
                asm volatile("mma.sync.aligned.m16n8k16.row.col.f32.f16.f16.f32 "
                             "{%0,%1,%2,%3},{%4,%5,%6,%7},{%8,%9},{%0,%1,%2,%3};"
                             : "+f"(acc[i][j][0]), "+f"(acc[i][j][1]),
                               "+f"(acc[i][j][2]), "+f"(acc[i][j][3])
                             : "r"(af[i].x), "r"(af[i].y), "r"(af[i].z), "r"(af[i].w),
                               "r"(bf[j].x), "r"(bf[j].y));
    }
    float sl[4][2] = {}, stm[4][2] = {};
#pragma unroll
    for (int i = 0; i < 4; i++) {
#pragma unroll
        for (int j = 0; j < 4; j++) {
            int cb = n0 + wn + j * 8 + (lane & 3) * 2;
            float b0 = (cb < OUTC) ? __ldg(&fc_b[cb]) : 0.f;
            float b1 = (cb + 1 < OUTC) ? __ldg(&fc_b[cb + 1]) : 0.f;
#pragma unroll
            for (int h = 0; h < 2; h++) {
                int gm = m0 + wm + i * 16 + (lane >> 2) + h * 8;
                float v0 = acc[i][j][h * 2 + 0] + b0;
                float v1 = acc[i][j][h * 2 + 1] + b1;
                // exp pair via one MUFU f16x2 op: exp(v) = 2^(v*log2e)
                uint32_t xr = pk(v0 * LOG2E, v1 * LOG2E);
                uint32_t er;
                asm("ex2.approx.f16x2 %0, %1;" : "=r"(er) : "r"(xr));
                float2 ef = __half22float2(u2h(er));
                if (cb < OUTL) {
                    *(float2*)&out_loc[(size_t)gm * OUTL + cb] = make_float2(v0, v1);
                    sl[i][h] += ef.x + ef.y;
                } else if (cb < OUTC) {
                    *(float2*)&out_tm[(size_t)gm * TDIM + (cb - OUTL)] = make_float2(v0, v1);
                    stm[i][h] += ef.x + ef.y;
                }
            }
        }
    }
    __shared__ float sp_loc[128][4];
    __shared__ float sp_tm[128][4];
#pragma unroll
    for (int i = 0; i < 4; i++)
#pragma unroll
        for (int h = 0; h < 2; h++) {
            float v = sl[i][h];
            v += __shfl_xor_sync(0xffffffffu, v, 1);
            v += __shfl_xor_sync(0xffffffffu, v, 2);
            float vt = stm[i][h];
            vt += __shfl_xor_sync(0xffffffffu, vt, 1);
            vt += __shfl_xor_sync(0xffffffffu, vt, 2);
            if ((lane & 3) == 0) {
                int lr = wm + i * 16 + (lane >> 2) + h * 8;
                sp_loc[lr][w & 3] = v;
                sp_tm[lr][w & 3] = vt;
            }
        }
    __syncthreads();
    if (threadIdx.x < 128) {
        int lr = threadIdx.x;
        float p = ((sp_loc[lr][0] + sp_loc[lr][1]) + sp_loc[lr][2]) + sp_loc[lr][3];
        g_ploc[(size_t)blockIdx.x * MROWS + m0 + lr] = p;
        if (blockIdx.x == NTILES - 1)
            g_ptm[m0 + lr] = ((sp_tm[lr][0] + sp_tm[lr][1]) + sp_tm[lr][2]) + sp_tm[lr][3];
    }
}

// ------------------ K5: logsumexp reduce (coalesced, deterministic) --------
__global__ void k_lse() {
    int r = blockIdx.x * blockDim.x + threadIdx.x;
    if (r >= MROWS) return;
    float s = 0.f;
    for (int i = 0; i < NTILES; i++) s += g_ploc[(size_t)i * MROWS + r];
    g_lse[r * 2 + 0] = logf(s);
    g_lse[r * 2 + 1] = logf(g_ptm[r]);
}

// ------------------ K6: in-place normalize ------------------
__global__ void k_norm(float* __restrict__ out) {
    const long long NL4 = (long long)MROWS * OUTL / 4;
    const long long NT4 = (long long)MROWS * TDIM / 4;
    long long idx = (long long)blockIdx.x * blockDim.x + threadIdx.x;
    if (idx >= NL4 + NT4) return;
    float4* o4 = (float4*)out;
    float l;
    if (idx < NL4) {
        int row = (int)((idx * 4) / OUTL);
        l = g_lse[row * 2];
    } else {
        long long i = idx - NL4;
        int row = (int)((i * 4) / TDIM);
        l = g_lse[row * 2 + 1];
    }
    float4 v = o4[idx];
    v.x -= l; v.y -= l; v.z -= l; v.w -= l;
    o4[idx] = v;
}

// ------------------ launch ------------------
extern "C" void kernel_launch(void* const* d_in, const int* in_sizes, int n_in,
                              void* d_out, int out_size) {
    (void)in_sizes; (void)n_in; (void)out_size;
    const int*   loc  = (const int*)d_in[0];
    const int*   tim  = (const int*)d_in[1];
    const int*   lab  = (const int*)d_in[2];
    const float* emb  = (const float*)d_in[3];
    const float* traj = (const float*)d_in[4];
    const float* fw   = (const float*)d_in[5];
    const float* fb   = (const float*)d_in[6];
    const float* wih0 = (const float*)d_in[7];
    const float* whh0 = (const float*)d_in[8];
    const float* bih0 = (const float*)d_in[9];
    const float* bhh0 = (const float*)d_in[10];
    const float* wih1 = (const float*)d_in[11];
    const float* whh1 = (const float*)d_in[12];
    const float* bih1 = (const float*)d_in[13];
    const float* bhh1 = (const float*)d_in[14];
    float* out = (float*)d_out;

    void *pX0, *pXP, *pY0, *pY1;
    cudaGetSymbolAddress(&pX0, g_X0);
    cudaGetSymbolAddress(&pXP, g_XP);
    cudaGetSymbolAddress(&pY0, g_Y0);
    cudaGetSymbolAddress(&pY1, g_Y1);

    k_embed<<<(MROWS * DIN + 255) / 256, 256>>>(loc, tim, emb, (float*)pX0);
    k_packB<<<((NPAD / 8) * 16 * 32 + 255) / 256, 256>>>(fw);

    k_gemm64<<<dim3(GDIM / 64, MROWS / 64), 256>>>((const float*)pX0, wih0, bih0,
                                                   (float*)pXP, MROWS, GDIM, DIN);
    k_rec<<<128, 384>>>((const float*)pXP, whh0, bhh0, traj, lab, (float*)pY0, 0);

    k_gemm64<<<dim3(GDIM / 64, MROWS / 64), 256>>>((const float*)pY0, wih1, bih1,
                                                   (float*)pXP, MROWS, GDIM, HDIM);
    k_rec<<<128, 384>>>((const float*)pXP, whh1, bhh1, traj, lab, (float*)pY1, 1);

    k_packA<<<((MROWS / 16) * 16 * 32 + 255) / 256, 256>>>();

    float* out_tm = out + (size_t)MROWS * OUTL;
    k_fc<<<dim3(NTILES, MROWS / 128), 256>>>(fb, out, out_tm);
    k_lse<<<(MROWS + 255) / 256, 256>>>();

    long long tot4 = (long long)MROWS * OUTL / 4 + (long long)MROWS * TDIM / 4;
    k_norm<<<(unsigned)((tot4 + 255) / 256), 256>>>(out);
}

// round 17
// speedup vs baseline: 1.3794x; 1.3794x over previous
#include <cuda_runtime.h>
#include <cuda_fp16.h>
#include <cstdint>

#define BATCH 32
#define TSEQ  48
#define EDIM  128
#define TDIM  48
#define DIN   176
#define HDIM  256
#define GDIM  768
#define OUTL  40000
#define OUTC  40048
#define MROWS 1536
#define NTILES 313            /* ceil(40048/128) */
#define NPAD  (NTILES * 128)  /* 40064 */
#define LOG2E 1.4426950408889634f

// ------------------ device scratch (no allocation allowed) ------------------
__device__ float g_X0[MROWS * DIN];
__device__ float g_XP[MROWS * GDIM];
__device__ float g_Y0[MROWS * HDIM];
__device__ uint4 g_Apack[(MROWS / 16) * 16 * 32];
__device__ uint2 g_Bpack[(NPAD / 8) * 16 * 32];
__device__ float g_ploc[NTILES * MROWS];   // [tile][row] for coalesced reduce
__device__ float g_ptm[MROWS];
__device__ float g_lse[MROWS * 2];

// ------------------ helpers ------------------
__device__ __forceinline__ uint32_t smem_u32(const void* p) {
    uint32_t a;
    asm("{ .reg .u64 t; cvta.to.shared.u64 t, %1; cvt.u32.u64 %0, t; }" : "=r"(a) : "l"(p));
    return a;
}
__device__ __forceinline__ uint32_t pk(float a, float b) {
    __half2 h = __floats2half2_rn(a, b);
    return *(uint32_t*)&h;
}
__device__ __forceinline__ __half2 u2h(uint32_t v) { return *(__half2*)&v; }
__device__ __forceinline__ void cluster_barrier() {
    asm volatile("barrier.cluster.arrive.aligned;\n\tbarrier.cluster.wait.aligned;" ::: "memory");
}
__device__ __forceinline__ void mbar_init(uint32_t mbar, uint32_t cnt) {
    asm volatile("mbarrier.init.shared.b64 [%0], %1;" :: "r"(mbar), "r"(cnt) : "memory");
}
__device__ __forceinline__ void mbar_expect_tx(uint32_t mbar, uint32_t bytes) {
    asm volatile("mbarrier.arrive.expect_tx.shared.b64 _, [%0], %1;"
                 :: "r"(mbar), "r"(bytes) : "memory");
}
__device__ __forceinline__ void mbar_wait(uint32_t mbar, uint32_t parity) {
    asm volatile(
        "{\n\t"
        ".reg .pred P;\n\t"
        "LAB_WAIT_%=:\n\t"
        "mbarrier.try_wait.parity.acquire.cluster.shared::cta.b64 P, [%0], %1, 0x989680;\n\t"
        "@P bra LAB_DONE_%=;\n\t"
        "bra LAB_WAIT_%=;\n\t"
        "LAB_DONE_%=:\n\t"
        "}"
        :: "r"(mbar), "r"(parity) : "memory");
}
// store 4 bytes into remote CTA rk's smem with tx-arrive on its mbarrier
__device__ __forceinline__ void st_async_remote(uint32_t laddr, uint32_t lmbar,
                                                uint32_t rk, uint32_t val) {
    asm volatile(
        "{\n\t"
        ".reg .b32 ra, rb;\n\t"
        "mapa.shared::cluster.u32 ra, %0, %2;\n\t"
        "mapa.shared::cluster.u32 rb, %1, %2;\n\t"
        "st.async.shared::cluster.mbarrier::complete_tx::bytes.b32 [ra], %3, [rb];\n\t"
        "}"
        :: "r"(laddr), "r"(lmbar), "r"(rk), "r"(val) : "memory");
}

// ------------------ K0: embedding gather + one-hot time ------------------
__global__ void k_embed(const int* __restrict__ loc, const int* __restrict__ tim,
                        const float* __restrict__ emb, float* __restrict__ X0) {
    int idx = blockIdx.x * blockDim.x + threadIdx.x;
    if (idx >= MROWS * DIN) return;
    int m = idx / DIN, c = idx - m * DIN;
    float v;
    if (c < EDIM) v = emb[(size_t)loc[m] * EDIM + c];
    else          v = (tim[m] == (c - EDIM)) ? 1.0f : 0.0f;
    X0[idx] = v;
}

// ------------------ K1: fp32 GEMM  C[M,N] = A[M,K] @ W[N,K]^T + bias -------
__global__ void __launch_bounds__(256) k_gemm64(const float* __restrict__ A,
                                                const float* __restrict__ W,
                                                const float* __restrict__ bias,
                                                float* __restrict__ C,
                                                int M, int N, int K) {
    __shared__ float As[16][68];
    __shared__ float Bs[16][68];
    int tid = threadIdx.x;
    int bm = blockIdx.y * 64, bn = blockIdx.x * 64;
    int tx = tid & 15, ty = tid >> 4;
    int lr = tid >> 2, lc = (tid & 3) * 4;
    float acc[4][4] = {};
    for (int k0 = 0; k0 < K; k0 += 16) {
        float4 a = *(const float4*)(A + (size_t)(bm + lr) * K + k0 + lc);
        float4 w = *(const float4*)(W + (size_t)(bn + lr) * K + k0 + lc);
        As[lc + 0][lr] = a.x; As[lc + 1][lr] = a.y; As[lc + 2][lr] = a.z; As[lc + 3][lr] = a.w;
        Bs[lc + 0][lr] = w.x; Bs[lc + 1][lr] = w.y; Bs[lc + 2][lr] = w.z; Bs[lc + 3][lr] = w.w;
        __syncthreads();
#pragma unroll
        for (int kk = 0; kk < 16; kk++) {
            float4 av = *(const float4*)&As[kk][ty * 4];
            float4 bv = *(const float4*)&Bs[kk][tx * 4];
            float aa[4] = {av.x, av.y, av.z, av.w};
            float bb[4] = {bv.x, bv.y, bv.z, bv.w};
#pragma unroll
            for (int i = 0; i < 4; i++)
#pragma unroll
                for (int j = 0; j < 4; j++) acc[i][j] += aa[i] * bb[j];
        }
        __syncthreads();
    }
#pragma unroll
    for (int i = 0; i < 4; i++)
#pragma unroll
        for (int j = 0; j < 4; j++) {
            int n = bn + tx * 4 + j;
            C[(size_t)(bm + ty * 4 + i) * N + n] = acc[i][j] + bias[n];
        }
}

// ------------------ K2: GRU recurrence -------------------------------------
// Cluster of 4 CTAs per batch element; 384 threads/CTA. Weights in registers.
// ALL 48 steps of this CTA's xp slice staged in smem up-front. Cross-CTA h
// exchange via st.async + dual mbarriers. Layer 0 writes y (fp32, for the
// next input-projection GEMM); layer 1 writes relu-packed fp16 pairs DIRECTLY
// into the mma A-fragment layout (k_packA fused away).
__global__ void __launch_bounds__(384, 1) __cluster_dims__(4, 1, 1)
k_rec(const float* __restrict__ xp, const float* __restrict__ w_hh,
      const float* __restrict__ b_hh, const float* __restrict__ traj,
      const int* __restrict__ labels, float* __restrict__ y,
      uint32_t* __restrict__ apack, int layer) {
    __shared__ uint32_t HH[256];        // [2][128] half2 (double-buffered h)
    __shared__ float PP[384];           // half-row partial dots
    __shared__ float XPS[TSEQ * 192];   // all 48 steps of xp slice (36.9 KB)
    __shared__ __align__(8) unsigned long long MB[2];
    const int tid = threadIdx.x;
    const int b = blockIdx.x >> 2, part = blockIdx.x & 3;
    const uint32_t mb0 = smem_u32(&MB[0]);

    if (tid == 0) { mbar_init(mb0, 1); mbar_init(mb0 + 8, 1); }

    // register-resident weights: each thread owns half (128 elems) of one row
    const int half = (tid >= 192) ? 1 : 0;
    const int r = tid - half * 192;                    // 0..191
    const int row = (r >> 6) * 256 + part * 64 + (r & 63);
    const float* wr = w_hh + (size_t)row * 256 + half * 128;
    uint4 wreg[16];
#pragma unroll
    for (int k = 0; k < 16; k++) {
        float4 a = *(const float4*)(wr + k * 8);
        float4 c = *(const float4*)(wr + k * 8 + 4);
        wreg[k] = make_uint4(pk(a.x, a.y), pk(a.z, a.w), pk(c.x, c.y), pk(c.z, c.w));
    }

    const int lb = labels[layer * 16 + (b >> 1)];
    const float* h0p = traj + (size_t)lb * 512 + (b & 1) * 256;
    if (tid < 128) HH[tid] = pk(h0p[2 * tid], h0p[2 * tid + 1]);
    float h_own = (tid < 64) ? h0p[part * 64 + tid] : 0.f;
    float bhr = 0.f, bhz = 0.f, bhn = 0.f;
    if (tid < 64) {
        bhr = b_hh[part * 64 + tid];
        bhz = b_hh[256 + part * 64 + tid];
        bhn = b_hh[512 + part * 64 + tid];
    }
    // stage the whole xp slice
    {
        const float* xb = xp + (size_t)(b * 48) * 768 + part * 64;
        for (int i = tid; i < TSEQ * 192; i += 384) {
            int t = i / 192, s = i - t * 192;
            XPS[i] = xb[(size_t)t * 768 + (s >> 6) * 256 + (s & 63)];
        }
    }
    __syncthreads();
    cluster_barrier();   // mbarriers + initial HH visible cluster-wide

    for (int t = 0; t < 48; t++) {
        if (t >= 1) mbar_wait(mb0 + ((t - 1) & 1) * 8, ((t - 1) >> 1) & 1);
        if (tid == 0 && t < 47) mbar_expect_tx(mb0 + (t & 1) * 8, 512);
        {
            const uint4* h4 = (const uint4*)HH + (t & 1) * 32 + half * 16;
            float acc0 = 0.f, acc1 = 0.f;
#pragma unroll
            for (int k = 0; k < 16; k += 4) {
                uint4 ha = h4[k], hb = h4[k + 1], hc = h4[k + 2], hd = h4[k + 3];
                __half2 c0 = __float2half2_rn(0.f);
                c0 = __hfma2(u2h(wreg[k].x), u2h(ha.x), c0);
                c0 = __hfma2(u2h(wreg[k].y), u2h(ha.y), c0);
                c0 = __hfma2(u2h(wreg[k].z), u2h(ha.z), c0);
                c0 = __hfma2(u2h(wreg[k].w), u2h(ha.w), c0);
                c0 = __hfma2(u2h(wreg[k + 1].x), u2h(hb.x), c0);
                c0 = __hfma2(u2h(wreg[k + 1].y), u2h(hb.y), c0);
                c0 = __hfma2(u2h(wreg[k + 1].z), u2h(hb.z), c0);
                c0 = __hfma2(u2h(wreg[k + 1].w), u2h(hb.w), c0);
                __half2 c1 = __float2half2_rn(0.f);
                c1 = __hfma2(u2h(wreg[k + 2].x), u2h(hc.x), c1);
                c1 = __hfma2(u2h(wreg[k + 2].y), u2h(hc.y), c1);
                c1 = __hfma2(u2h(wreg[k + 2].z), u2h(hc.z), c1);
                c1 = __hfma2(u2h(wreg[k + 2].w), u2h(hc.w), c1);
                c1 = __hfma2(u2h(wreg[k + 3].x), u2h(hd.x), c1);
                c1 = __hfma2(u2h(wreg[k + 3].y), u2h(hd.y), c1);
                c1 = __hfma2(u2h(wreg[k + 3].z), u2h(hd.z), c1);
                c1 = __hfma2(u2h(wreg[k + 3].w), u2h(hd.w), c1);
                float2 f0 = __half22float2(c0);
                float2 f1 = __half22float2(c1);
                acc0 += f0.x + f0.y;
                acc1 += f1.x + f1.y;
            }
            PP[tid] = acc0 + acc1;
        }
        __syncthreads();
        if (tid < 64) {
            const float* xc = XPS + t * 192;
            float hr = PP[tid] + PP[192 + tid] + bhr;
            float hz = PP[64 + tid] + PP[256 + tid] + bhz;
            float hn = PP[128 + tid] + PP[320 + tid] + bhn;
            float r2 = 1.f / (1.f + __expf(-(xc[tid] + hr)));
            float z = 1.f / (1.f + __expf(-(xc[64 + tid] + hz)));
            float n = tanhf(xc[128 + tid] + r2 * hn);
            float hv = (1.f - z) * n + z * h_own;
            h_own = hv;
            float hvo = __shfl_xor_sync(0xffffffffu, hv, 1);
            const int m = b * 48 + t;
            if (layer == 0) {
                y[(size_t)m * 256 + part * 64 + tid] = hv;
            } else if (!(tid & 1)) {
                // fused packA: relu + fp16 pair into mma A-fragment layout
                int c = part * 64 + tid;
                int lane = ((m & 7) << 2) | ((tid & 7) >> 1);
                int comp = (((m & 15) >= 8) ? 1 : 0) | (((tid & 15) >= 8) ? 2 : 0);
                int gidx = (((m >> 4) * 16 + (c >> 4)) * 32 + lane) * 4 + comp;
                apack[gidx] = pk(fmaxf(hv, 0.f), fmaxf(hvo, 0.f));
            }
            if (!(tid & 1) && t < 47) {
                uint32_t pv = pk(hv, hvo);
                uint32_t la = smem_u32(&HH[((t + 1) & 1) * 128 + ((part * 64 + tid) >> 1)]);
                uint32_t lm = mb0 + (t & 1) * 8;
#pragma unroll
                for (int rk = 0; rk < 4; rk++) st_async_remote(la, lm, rk, pv);
            }
        }
    }
    cluster_barrier();   // no CTA exits while peers' st.asyncs may target it
}

// ------------------ K3: B operand packing for fp16 mma ------------------
__global__ void k_packB(const float* __restrict__ fw) {
    int g = blockIdx.x * blockDim.x + threadIdx.x;
    if (g >= (NPAD / 8) * 16 * 32) return;
    int lane = g & 31, kt = (g >> 5) & 15, nt = g >> 9;
    int n = nt * 8 + (lane >> 2);
    int k0 = kt * 16 + (lane & 3) * 2;
    float w00 = 0.f, w01 = 0.f, w08 = 0.f, w09 = 0.f;
    if (n < OUTC) {
        const float* r = fw + (size_t)n * HDIM + k0;
        w00 = r[0]; w01 = r[1]; w08 = r[8]; w09 = r[9];
    }
    g_Bpack[g] = make_uint2(pk(w00, w01), pk(w08, w09));
}

// ------------------ K4: fc GEMM (fp16 mma, fp32 acc) + write + exp sums ----
__global__ void __launch_bounds__(256) k_fc(const float* __restrict__ fc_b,
                                            float* __restrict__ out_loc,
                                            float* __restrict__ out_tm) {
    const int lane = threadIdx.x & 31, w = threadIdx.x >> 5;
    const int wm = (w >> 2) * 64, wn = (w & 3) * 32;
    const int m0 = blockIdx.y * 128, n0 = blockIdx.x * 128;
    const int mtb = (m0 + wm) >> 4, ntb = (n0 + wn) >> 3;
    float acc[4][4][4];
#pragma unroll
    for (int i = 0; i < 4; i++)
#pragma unroll
        for (int j = 0; j < 4; j++) {
            acc[i][j][0] = 0.f; acc[i][j][1] = 0.f; acc[i][j][2] = 0.f; acc[i][j][3] = 0.f;
        }
    for (int kt = 0; kt < 16; kt++) {
        uint4 af[4]; uint2 bf[4];
#pragma unroll
        for (int i = 0; i < 4; i++) af[i] = g_Apack[((size_t)(mtb + i) * 16 + kt) * 32 + lane];
#pragma unroll
        for (int j = 0; j < 4; j++) bf[j] = g_Bpack[((size_t)(ntb + j) * 16 + kt) * 32 + lane];
#pragma unroll
        for (int i = 0; i < 4; i++)
#pragma unroll
            for (int j = 0; j < 4; j++)
                asm volatile("mma.sync.aligned.m16n8k16.row.col.f32.f16.f16.f32 "
                             "{%0,%1,%2,%3},{%4,%5,%6,%7},{%8,%9},{%0,%1,%2,%3};"
                             : "+f"(acc[i][j][0]), "+f"(acc[i][j][1]),
                               "+f"(acc[i][j][2]), "+f"(acc[i][j][3])
                             : "r"(af[i].x), "r"(af[i].y), "r"(af[i].z), "r"(af[i].w),
                               "r"(bf[j].x), "r"(bf[j].y));
    }
    float sl[4][2] = {}, stm[4][2] = {};
#pragma unroll
    for (int i = 0; i < 4; i++) {
#pragma unroll
        for (int j = 0; j < 4; j++) {
            int cb = n0 + wn + j * 8 + (lane & 3) * 2;
            float b0 = (cb < OUTC) ? __ldg(&fc_b[cb]) : 0.f;
            float b1 = (cb + 1 < OUTC) ? __ldg(&fc_b[cb + 1]) : 0.f;
#pragma unroll
            for (int h = 0; h < 2; h++) {
                int gm = m0 + wm + i * 16 + (lane >> 2) + h * 8;
                float v0 = acc[i][j][h * 2 + 0] + b0;
                float v1 = acc[i][j][h * 2 + 1] + b1;
                // exp pair via one MUFU f16x2 op: exp(v) = 2^(v*log2e)
                uint32_t xr = pk(v0 * LOG2E, v1 * LOG2E);
                uint32_t er;
                asm("ex2.approx.f16x2 %0, %1;" : "=r"(er) : "r"(xr));
                float2 ef = __half22float2(u2h(er));
                if (cb < OUTL) {
                    *(float2*)&out_loc[(size_t)gm * OUTL + cb] = make_float2(v0, v1);
                    sl[i][h] += ef.x + ef.y;
                } else if (cb < OUTC) {
                    *(float2*)&out_tm[(size_t)gm * TDIM + (cb - OUTL)] = make_float2(v0, v1);
                    stm[i][h] += ef.x + ef.y;
                }
            }
        }
    }
    __shared__ float sp_loc[128][4];
    __shared__ float sp_tm[128][4];
#pragma unroll
    for (int i = 0; i < 4; i++)
#pragma unroll
        for (int h = 0; h < 2; h++) {
            float v = sl[i][h];
            v += __shfl_xor_sync(0xffffffffu, v, 1);
            v += __shfl_xor_sync(0xffffffffu, v, 2);
            float vt = stm[i][h];
            vt += __shfl_xor_sync(0xffffffffu, vt, 1);
            vt += __shfl_xor_sync(0xffffffffu, vt, 2);
            if ((lane & 3) == 0) {
                int lr = wm + i * 16 + (lane >> 2) + h * 8;
                sp_loc[lr][w & 3] = v;
                sp_tm[lr][w & 3] = vt;
            }
        }
    __syncthreads();
    if (threadIdx.x < 128) {
        int lr = threadIdx.x;
        float p = ((sp_loc[lr][0] + sp_loc[lr][1]) + sp_loc[lr][2]) + sp_loc[lr][3];
        g_ploc[(size_t)blockIdx.x * MROWS + m0 + lr] = p;
        if (blockIdx.x == NTILES - 1)
            g_ptm[m0 + lr] = ((sp_tm[lr][0] + sp_tm[lr][1]) + sp_tm[lr][2]) + sp_tm[lr][3];
    }
}

// ------------------ K5: logsumexp reduce (coalesced, deterministic) --------
__global__ void k_lse() {
    int r = blockIdx.x * blockDim.x + threadIdx.x;
    if (r >= MROWS) return;
    float s = 0.f;
    for (int i = 0; i < NTILES; i++) s += g_ploc[(size_t)i * MROWS + r];
    g_lse[r * 2 + 0] = logf(s);
    g_lse[r * 2 + 1] = logf(g_ptm[r]);
}

// ------------------ K6: in-place normalize ------------------
__global__ void k_norm(float* __restrict__ out) {
    const long long NL4 = (long long)MROWS * OUTL / 4;
    const long long NT4 = (long long)MROWS * TDIM / 4;
    long long idx = (long long)blockIdx.x * blockDim.x + threadIdx.x;
    if (idx >= NL4 + NT4) return;
    float4* o4 = (float4*)out;
    float l;
    if (idx < NL4) {
        int row = (int)((idx * 4) / OUTL);
        l = g_lse[row * 2];
    } else {
        long long i = idx - NL4;
        int row = (int)((i * 4) / TDIM);
        l = g_lse[row * 2 + 1];
    }
    float4 v = o4[idx];
    v.x -= l; v.y -= l; v.z -= l; v.w -= l;
    o4[idx] = v;
}

// ------------------ launch ------------------
extern "C" void kernel_launch(void* const* d_in, const int* in_sizes, int n_in,
                              void* d_out, int out_size) {
    (void)in_sizes; (void)n_in; (void)out_size;
    const int*   loc  = (const int*)d_in[0];
    const int*   tim  = (const int*)d_in[1];
    const int*   lab  = (const int*)d_in[2];
    const float* emb  = (const float*)d_in[3];
    const float* traj = (const float*)d_in[4];
    const float* fw   = (const float*)d_in[5];
    const float* fb   = (const float*)d_in[6];
    const float* wih0 = (const float*)d_in[7];
    const float* whh0 = (const float*)d_in[8];
    const float* bih0 = (const float*)d_in[9];
    const float* bhh0 = (const float*)d_in[10];
    const float* wih1 = (const float*)d_in[11];
    const float* whh1 = (const float*)d_in[12];
    const float* bih1 = (const float*)d_in[13];
    const float* bhh1 = (const float*)d_in[14];
    float* out = (float*)d_out;

    void *pX0, *pXP, *pY0, *pAp;
    cudaGetSymbolAddress(&pX0, g_X0);
    cudaGetSymbolAddress(&pXP, g_XP);
    cudaGetSymbolAddress(&pY0, g_Y0);
    cudaGetSymbolAddress(&pAp, g_Apack);

    k_embed<<<(MROWS * DIN + 255) / 256, 256>>>(loc, tim, emb, (float*)pX0);
    k_packB<<<((NPAD / 8) * 16 * 32 + 255) / 256, 256>>>(fw);

    k_gemm64<<<dim3(GDIM / 64, MROWS / 64), 256>>>((const float*)pX0, wih0, bih0,
                                                   (float*)pXP, MROWS, GDIM, DIN);
    k_rec<<<128, 384>>>((const float*)pXP, whh0, bhh0, traj, lab,
                        (float*)pY0, (uint32_t*)pAp, 0);

    k_gemm64<<<dim3(GDIM / 64, MROWS / 64), 256>>>((const float*)pY0, wih1, bih1,
                                                   (float*)pXP, MROWS, GDIM, HDIM);
    k_rec<<<128, 384>>>((const float*)pXP, whh1, bhh1, traj, lab,
                        (float*)pY0, (uint32_t*)pAp, 1);

    float* out_tm = out + (size_t)MROWS * OUTL;
    k_fc<<<dim3(NTILES, MROWS / 128), 256>>>(fb, out, out_tm);
    k_lse<<<(MROWS + 255) / 256, 256>>>();

    long long tot4 = (long long)MROWS * OUTL / 4 + (long long)MROWS * TDIM / 4;
    k_norm<<<(unsigned)((tot4 + 255) / 256), 256>>>(out);
}